// round 4
// baseline (speedup 1.0000x reference)
#include <cuda_runtime.h>
#include <math.h>
#include <stdint.h>

#define Bc 32
#define Vc 8192
#define Tc 16
#define KS 4
#define VCH 32
#define EMB_SCALE 22.627416997969522f

__device__ float g_x[Bc * 512];
__device__ float g_y[Bc * 512];
__device__ float g_qkvp[KS * Bc * 1536];
__device__ float g_ff1p[KS * Bc * 2048];
__device__ float g_logp[KS * Bc * Vc];
__device__ float g_logits[Bc * Vc];
__device__ float g_sample[Bc * Vc];
__device__ float g_hp[VCH * Bc * 512];
__device__ float g_ca[4 * Bc * 512];
__device__ float g_Kc[4 * Tc * Bc * 512];
__device__ float g_Vca[4 * Tc * Bc * 512];

__device__ __forceinline__ float2 blockSum2(float a, float b) {
    __shared__ float sh[16];
    #pragma unroll
    for (int o = 16; o; o >>= 1) {
        a += __shfl_xor_sync(0xffffffffu, a, o);
        b += __shfl_xor_sync(0xffffffffu, b, o);
    }
    int w = threadIdx.x >> 5;
    if ((threadIdx.x & 31) == 0) { sh[w] = a; sh[8 + w] = b; }
    __syncthreads();
    float ra = sh[0]+sh[1]+sh[2]+sh[3]+sh[4]+sh[5]+sh[6]+sh[7];
    float rb = sh[8]+sh[9]+sh[10]+sh[11]+sh[12]+sh[13]+sh[14]+sh[15];
    __syncthreads();
    return make_float2(ra, rb);
}

__device__ __forceinline__ float2 blockMax2(float a, float b) {
    __shared__ float sh[16];
    #pragma unroll
    for (int o = 16; o; o >>= 1) {
        a = fmaxf(a, __shfl_xor_sync(0xffffffffu, a, o));
        b = fmaxf(b, __shfl_xor_sync(0xffffffffu, b, o));
    }
    int w = threadIdx.x >> 5;
    if ((threadIdx.x & 31) == 0) { sh[w] = a; sh[8 + w] = b; }
    __syncthreads();
    float ra = sh[0], rb = sh[8];
    #pragma unroll
    for (int i = 1; i < 8; i++) { ra = fmaxf(ra, sh[i]); rb = fmaxf(rb, sh[8+i]); }
    __syncthreads();
    return make_float2(ra, rb);
}

__device__ __forceinline__ float geluf(float x) {
    return 0.5f * x * (1.0f + erff(x * 0.70710678118654752f));
}

// C_partial[32,N] = g_x[32,512] @ W[N,512]^T ; grid(N/64, KS), 128 thr
__global__ __launch_bounds__(128) void gemm512p(const float* __restrict__ W,
                                                float* __restrict__ Cp, int N) {
    __shared__ float Xs[32][33];
    __shared__ float Ws[64][33];
    int tid = threadIdx.x, r0 = (tid & 7) * 4, c0 = (tid >> 3) * 4;
    int nb = blockIdx.x * 64, kb = blockIdx.y * (512 / KS);
    float acc[4][4] = {};
    for (int kc = kb; kc < kb + (512 / KS); kc += 32) {
        for (int i = tid; i < 1024; i += 128)
            Xs[i >> 5][i & 31] = g_x[(i >> 5) * 512 + kc + (i & 31)];
        for (int i = tid; i < 2048; i += 128)
            Ws[i >> 5][i & 31] = W[(size_t)(nb + (i >> 5)) * 512 + kc + (i & 31)];
        __syncthreads();
        #pragma unroll
        for (int k = 0; k < 32; k++) {
            float xa[4], wa[4];
            #pragma unroll
            for (int i = 0; i < 4; i++) xa[i] = Xs[r0 + i][k];
            #pragma unroll
            for (int j = 0; j < 4; j++) wa[j] = Ws[c0 + j][k];
            #pragma unroll
            for (int i = 0; i < 4; i++)
                #pragma unroll
                for (int j = 0; j < 4; j++) acc[i][j] += xa[i] * wa[j];
        }
        __syncthreads();
    }
    float* Co = Cp + (size_t)blockIdx.y * 32 * N;
    #pragma unroll
    for (int i = 0; i < 4; i++)
        #pragma unroll
        for (int j = 0; j < 4; j++)
            Co[(size_t)(r0 + i) * N + nb + c0 + j] = acc[i][j];
}

// g_hp partials = g_sample[32,Vc-chunk] @ Wemb[Vc,512] ; grid(8, VCH), 128 thr
__global__ __launch_bounds__(128) void gemm_embed(const float* __restrict__ Wm) {
    __shared__ float Ss[32][33];
    __shared__ float Ws2[32][65];
    int tid = threadIdx.x, r0 = (tid & 7) * 4, c0 = (tid >> 3) * 4;
    int eb = blockIdx.x * 64, kb = blockIdx.y * (Vc / VCH);
    float acc[4][4] = {};
    for (int kc = kb; kc < kb + (Vc / VCH); kc += 32) {
        for (int i = tid; i < 1024; i += 128)
            Ss[i >> 5][i & 31] = g_sample[(size_t)(i >> 5) * Vc + kc + (i & 31)];
        for (int i = tid; i < 2048; i += 128)
            Ws2[i >> 6][i & 63] = Wm[(size_t)(kc + (i >> 6)) * 512 + eb + (i & 63)];
        __syncthreads();
        #pragma unroll
        for (int k = 0; k < 32; k++) {
            float xa[4], wa[4];
            #pragma unroll
            for (int i = 0; i < 4; i++) xa[i] = Ss[r0 + i][k];
            #pragma unroll
            for (int j = 0; j < 4; j++) wa[j] = Ws2[k][c0 + j];
            #pragma unroll
            for (int i = 0; i < 4; i++)
                #pragma unroll
                for (int j = 0; j < 4; j++) acc[i][j] += xa[i] * wa[j];
        }
        __syncthreads();
    }
    float* Co = g_hp + (size_t)blockIdx.y * 32 * 512;
    #pragma unroll
    for (int i = 0; i < 4; i++)
        #pragma unroll
        for (int j = 0; j < 4; j++)
            Co[(size_t)(r0 + i) * 512 + eb + c0 + j] = acc[i][j];
}

// qkv-sum+bias, KV write, attention, out-proj+residual, LN1, +CA, LN2
__global__ __launch_bounds__(256) void k_attn(int l, int s,
        const float* __restrict__ qkvb, const float* __restrict__ ow,
        const float* __restrict__ ob,
        const float* __restrict__ l1g, const float* __restrict__ l1b,
        const float* __restrict__ l2g, const float* __restrict__ l2b) {
    __shared__ float q[512], o[512], xb[512];
    int b = blockIdx.x, tid = threadIdx.x;
    const float* bp = qkvb + l * 1536;
    for (int e = tid; e < 512; e += 256) {
        float qq = bp[e], kk = bp[512 + e], vv = bp[1024 + e];
        #pragma unroll
        for (int p = 0; p < KS; p++) {
            const float* qp = g_qkvp + ((size_t)p * 32 + b) * 1536;
            qq += qp[e]; kk += qp[512 + e]; vv += qp[1024 + e];
        }
        q[e] = qq;
        g_Kc [((size_t)(l * Tc + s) * Bc + b) * 512 + e] = kk;
        g_Vca[((size_t)(l * Tc + s) * Bc + b) * 512 + e] = vv;
        xb[e] = g_x[b * 512 + e];
    }
    __syncthreads();
    int w = tid >> 5, lane = tid & 31;
    {   // one warp per head
        int h = w;
        float sc = -1e30f;
        if (lane <= s) {
            const float* kp = g_Kc + ((size_t)(l * Tc + lane) * Bc + b) * 512 + h * 64;
            const float* qp = q + h * 64;
            float a0 = 0.f, a1 = 0.f;
            #pragma unroll
            for (int d = 0; d < 64; d += 2) { a0 += qp[d]*kp[d]; a1 += qp[d+1]*kp[d+1]; }
            sc = (a0 + a1) * 0.125f;
        }
        float m = sc;
        #pragma unroll
        for (int off = 16; off; off >>= 1) m = fmaxf(m, __shfl_xor_sync(0xffffffffu, m, off));
        float ex = (lane <= s) ? expf(sc - m) : 0.f;
        float sum = ex;
        #pragma unroll
        for (int off = 16; off; off >>= 1) sum += __shfl_xor_sync(0xffffffffu, sum, off);
        float a = ex / sum;
        float o0 = 0.f, o1 = 0.f;
        for (int j = 0; j <= s; j++) {
            float aj = __shfl_sync(0xffffffffu, a, j);
            const float* vp = g_Vca + ((size_t)(l * Tc + j) * Bc + b) * 512 + h * 64;
            o0 += aj * vp[lane]; o1 += aj * vp[lane + 32];
        }
        o[h * 64 + lane] = o0; o[h * 64 + lane + 32] = o1;
    }
    __syncthreads();
    for (int e = w; e < 512; e += 8) {   // out-proj + residual -> q[]
        const float* wr = ow + ((size_t)l * 512 + e) * 512;
        float a0=0.f,a1=0.f,a2=0.f,a3=0.f;
        for (int k = lane; k < 512; k += 128) {
            a0 += wr[k]*o[k];       a1 += wr[k+32]*o[k+32];
            a2 += wr[k+64]*o[k+64]; a3 += wr[k+96]*o[k+96];
        }
        float acc = a0+a1+a2+a3;
        #pragma unroll
        for (int off = 16; off; off >>= 1) acc += __shfl_xor_sync(0xffffffffu, acc, off);
        if (lane == 0) q[e] = xb[e] + acc + ob[l * 512 + e];
    }
    __syncthreads();
    float s1 = 0.f, s2 = 0.f;
    for (int e = tid; e < 512; e += 256) { float v = q[e]; s1 += v; s2 += v*v; }
    float2 r = blockSum2(s1, s2);
    float mean = r.x * (1.f/512.f);
    float rstd = rsqrtf(r.y * (1.f/512.f) - mean*mean + 1e-5f);
    for (int e = tid; e < 512; e += 256)
        o[e] = (q[e]-mean)*rstd*l1g[l*512+e] + l1b[l*512+e] + g_ca[((size_t)l*32+b)*512+e];
    float t1 = 0.f, t2 = 0.f;
    for (int e = tid; e < 512; e += 256) { float v = o[e]; t1 += v; t2 += v*v; }
    r = blockSum2(t1, t2);
    mean = r.x * (1.f/512.f);
    rstd = rsqrtf(r.y * (1.f/512.f) - mean*mean + 1e-5f);
    for (int e = tid; e < 512; e += 256)
        g_x[b*512+e] = (o[e]-mean)*rstd*l2g[l*512+e] + l2b[l*512+e];
}

// y = x + gelu(ff1) @ w2^T + b2 ; grid 128 (b*4+quarter), 256 thr
__global__ __launch_bounds__(256) void k_ff2(int l, const float* __restrict__ b1,
        const float* __restrict__ w2, const float* __restrict__ b2) {
    __shared__ float hbuf[2048];
    int b = blockIdx.x >> 2, eq = blockIdx.x & 3, tid = threadIdx.x;
    for (int k = tid; k < 2048; k += 256) {
        float u = b1[l * 2048 + k];
        #pragma unroll
        for (int p = 0; p < KS; p++) u += g_ff1p[((size_t)p * 32 + b) * 2048 + k];
        hbuf[k] = geluf(u);
    }
    __syncthreads();
    int w = tid >> 5, lane = tid & 31;
    for (int ee = w; ee < 128; ee += 8) {
        int e = eq * 128 + ee;
        const float* wr = w2 + ((size_t)l * 512 + e) * 2048;
        float a0=0.f,a1=0.f,a2=0.f,a3=0.f;
        for (int k = lane; k < 2048; k += 128) {
            a0 += wr[k]*hbuf[k];       a1 += wr[k+32]*hbuf[k+32];
            a2 += wr[k+64]*hbuf[k+64]; a3 += wr[k+96]*hbuf[k+96];
        }
        float acc = a0+a1+a2+a3;
        #pragma unroll
        for (int off = 16; off; off >>= 1) acc += __shfl_xor_sync(0xffffffffu, acc, off);
        if (lane == 0) g_y[b*512+e] = g_x[b*512+e] + acc + b2[l*512+e];
    }
}

__global__ __launch_bounds__(256) void k_ln3(int l, const float* __restrict__ gg,
                                             const float* __restrict__ bb) {
    __shared__ float yb[512];
    int b = blockIdx.x, tid = threadIdx.x;
    for (int e = tid; e < 512; e += 256) yb[e] = g_y[b * 512 + e];
    __syncthreads();
    float s1 = 0.f, s2 = 0.f;
    for (int e = tid; e < 512; e += 256) { float v = yb[e]; s1 += v; s2 += v*v; }
    float2 r = blockSum2(s1, s2);
    float mean = r.x * (1.f/512.f);
    float rstd = rsqrtf(r.y * (1.f/512.f) - mean*mean + 1e-5f);
    for (int e = tid; e < 512; e += 256)
        g_x[b*512+e] = (yb[e]-mean)*rstd*gg[l*512+e] + bb[l*512+e];
}

// logits sum + two softmaxes; writes sequence row, distrib row, g_sample
__global__ __launch_bounds__(256) void k_stats(int s, const float* __restrict__ outb,
        const float* __restrict__ gum, float* __restrict__ out) {
    int b = blockIdx.x, tid = threadIdx.x;
    const float* gp = gum + ((size_t)s * Bc + b) * Vc;
    float* lg = g_logits + (size_t)b * Vc;
    float mx1 = -1e30f, mx2 = -1e30f;
    for (int v = tid; v < Vc; v += 256) {
        float x = outb[v];
        #pragma unroll
        for (int p = 0; p < KS; p++) x += g_logp[((size_t)p * 32 + b) * Vc + v];
        lg[v] = x;
        mx1 = fmaxf(mx1, x);
        mx2 = fmaxf(mx2, x + gp[v]);
    }
    float2 M = blockMax2(mx1, mx2);
    float z1 = 0.f, z2 = 0.f;
    for (int v = tid; v < Vc; v += 256) {
        float x = lg[v];
        z1 += expf(x - M.x);
        z2 += expf(x + gp[v] - M.y);
    }
    float2 Z = blockSum2(z1, z2);
    float i1 = 1.f / Z.x, i2 = 1.f / Z.y;
    float* seq = out + (size_t)b * (17 * Vc) + (size_t)s * Vc;
    float* dst = out + (size_t)Bc * 17 * Vc + ((size_t)s * Bc + b) * Vc;
    float* smp = g_sample + (size_t)b * Vc;
    for (int v = tid; v < Vc; v += 256) {
        float x = lg[v];
        dst[v] = expf(x - M.x) * i1;
        float sv = expf(x + gp[v] - M.y) * i2;
        seq[v] = sv;
        smp[v] = sv;
    }
}

__global__ __launch_bounds__(256) void k_begin() {
    int b = blockIdx.x, tid = threadIdx.x;
    for (int e = tid; e < 512; e += 256) {
        float a = 0.f;
        #pragma unroll
        for (int p = 0; p < VCH; p++) a += g_hp[((size_t)p * 32 + b) * 512 + e];
        g_x[b * 512 + e] = a * EMB_SCALE;
    }
}

__global__ __launch_bounds__(256) void k_setup(const float* __restrict__ spec,
                                               float* __restrict__ out) {
    int b = blockIdx.x, tid = threadIdx.x;
    for (int e = tid; e < 512; e += 256) g_x[b * 512 + e] = spec[e];
    float* seq = out + (size_t)b * (17 * Vc) + (size_t)16 * Vc;
    for (int v = tid; v < Vc; v += 256) seq[v] = (v == 0) ? 1.f : 0.f;
}

// cross-attn precompute: g_ca[l,b,:] = ca_out_w @ (wv@enc + bv) + ca_out_b
__global__ __launch_bounds__(256) void k_capre(const float* __restrict__ enc,
        const float* __restrict__ cw, const float* __restrict__ cb,
        const float* __restrict__ ow, const float* __restrict__ ob) {
    __shared__ float ebf[512], vv[512];
    int l = blockIdx.x >> 5, b = blockIdx.x & 31, tid = threadIdx.x;
    for (int e = tid; e < 512; e += 256) ebf[e] = enc[b * 512 + e];
    __syncthreads();
    int w = tid >> 5, lane = tid & 31;
    for (int e = w; e < 512; e += 8) {
        const float* wr = cw + ((size_t)l * 1536 + 1024 + e) * 512;
        float a0=0.f,a1=0.f,a2=0.f,a3=0.f;
        for (int k = lane; k < 512; k += 128) {
            a0 += wr[k]*ebf[k];       a1 += wr[k+32]*ebf[k+32];
            a2 += wr[k+64]*ebf[k+64]; a3 += wr[k+96]*ebf[k+96];
        }
        float acc = a0+a1+a2+a3;
        #pragma unroll
        for (int off = 16; off; off >>= 1) acc += __shfl_xor_sync(0xffffffffu, acc, off);
        if (lane == 0) vv[e] = acc + cb[l * 1536 + 1024 + e];
    }
    __syncthreads();
    for (int e = w; e < 512; e += 8) {
        const float* wr = ow + ((size_t)l * 512 + e) * 512;
        float a0=0.f,a1=0.f,a2=0.f,a3=0.f;
        for (int k = lane; k < 512; k += 128) {
            a0 += wr[k]*vv[k];       a1 += wr[k+32]*vv[k+32];
            a2 += wr[k+64]*vv[k+64]; a3 += wr[k+96]*vv[k+96];
        }
        float acc = a0+a1+a2+a3;
        #pragma unroll
        for (int off = 16; off; off >>= 1) acc += __shfl_xor_sync(0xffffffffu, acc, off);
        if (lane == 0) g_ca[((size_t)l * 32 + b) * 512 + e] = acc + ob[l * 512 + e];
    }
}

extern "C" void kernel_launch(void* const* d_in, const int* in_sizes, int n_in,
                              void* d_out, int out_size) {
    const float* enc  = (const float*)d_in[0];
    const float* spec = (const float*)d_in[1];
    const float* embw = (const float*)d_in[2];
    const float* outw = (const float*)d_in[3];
    const float* outb = (const float*)d_in[4];
    const float* gum  = (const float*)d_in[5];
    const float* saqw = (const float*)d_in[6];
    const float* saqb = (const float*)d_in[7];
    const float* saow = (const float*)d_in[8];
    const float* saob = (const float*)d_in[9];
    const float* caqw = (const float*)d_in[10];
    const float* caqb = (const float*)d_in[11];
    const float* caow = (const float*)d_in[12];
    const float* caob = (const float*)d_in[13];
    const float* l1g  = (const float*)d_in[14];
    const float* l1b  = (const float*)d_in[15];
    const float* l2g  = (const float*)d_in[16];
    const float* l2b  = (const float*)d_in[17];
    const float* l3g  = (const float*)d_in[18];
    const float* l3b  = (const float*)d_in[19];
    const float* w1   = (const float*)d_in[20];
    const float* b1   = (const float*)d_in[21];
    const float* w2   = (const float*)d_in[22];
    const float* b2   = (const float*)d_in[23];
    float* out = (float*)d_out;

    float *p_qkvp, *p_ff1p, *p_logp;
    cudaGetSymbolAddress((void**)&p_qkvp, g_qkvp);
    cudaGetSymbolAddress((void**)&p_ff1p, g_ff1p);
    cudaGetSymbolAddress((void**)&p_logp, g_logp);

    k_setup<<<32, 256>>>(spec, out);
    k_capre<<<128, 256>>>(enc, caqw, caqb, caow, caob);

    for (int s = 0; s < Tc; s++) {
        for (int l = 0; l < 4; l++) {
            gemm512p<<<dim3(24, KS), 128>>>(saqw + (size_t)l * 1536 * 512, p_qkvp, 1536);
            k_attn<<<32, 256>>>(l, s, saqb, saow, saob, l1g, l1b, l2g, l2b);
            gemm512p<<<dim3(32, KS), 128>>>(w1 + (size_t)l * 2048 * 512, p_ff1p, 2048);
            k_ff2<<<128, 256>>>(l, b1, w2, b2);
            k_ln3<<<32, 256>>>(l, l3g, l3b);
        }
        gemm512p<<<dim3(128, KS), 128>>>(outw, p_logp, Vc);
        k_stats<<<32, 256>>>(s, outb, gum, out);
        if (s < Tc - 1) {
            gemm_embed<<<dim3(8, VCH), 128>>>(embw);
            k_begin<<<32, 256>>>();
        }
    }
}

// round 5
// speedup vs baseline: 2.2459x; 2.2459x over previous
#include <cuda_runtime.h>
#include <math.h>
#include <stdint.h>

#define Bc 32
#define Vc 8192
#define Tc 16
#define EMB_SCALE 22.627416997969522f
#define KSQ 4
#define KSO 8
#define KSF1 4
#define KSF2 16
#define KSE 16

__device__ float g_x[Bc * 512];
__device__ float g_attn_o[Bc * 512];
__device__ float g_h[Bc * 2048];
__device__ float g_qkvp[KSQ * Bc * 1536];
__device__ float g_opp[KSO * Bc * 512];
__device__ float g_ff1p[KSF1 * Bc * 2048];
__device__ float g_ff2p[KSF2 * Bc * 512];
__device__ float g_embp[KSE * Bc * 512];
__device__ float g_logits[Bc * Vc];
__device__ float g_sample[Bc * Vc];
__device__ float g_ca[4 * Bc * 512];
__device__ float g_Kc[4 * Tc * Bc * 512];
__device__ float g_Vcc[4 * Tc * Bc * 512];

__device__ int g_count;
__device__ volatile int g_gen;

__shared__ float s_Xs[32 * 33];
__shared__ float s_Ws[64 * 33];
__shared__ float s_q[512];
__shared__ float s_o[512];

__device__ __forceinline__ void gsync() {
    __threadfence();
    __syncthreads();
    if (threadIdx.x == 0) {
        int gen = g_gen;
        if (atomicAdd(&g_count, 1) == (int)gridDim.x - 1) {
            g_count = 0;
            __threadfence();
            g_gen = gen + 1;
        } else {
            while (g_gen == gen) { }
        }
        __threadfence();   // acquire: CCTL.IVALL invalidates this SM's L1
    }
    __syncthreads();
}

__device__ __forceinline__ float2 blockSum2(float a, float b) {
    __shared__ float sh[16];
    #pragma unroll
    for (int o = 16; o; o >>= 1) {
        a += __shfl_xor_sync(0xffffffffu, a, o);
        b += __shfl_xor_sync(0xffffffffu, b, o);
    }
    int w = threadIdx.x >> 5;
    if ((threadIdx.x & 31) == 0) { sh[w] = a; sh[8 + w] = b; }
    __syncthreads();
    float ra = sh[0]+sh[1]+sh[2]+sh[3]+sh[4]+sh[5]+sh[6]+sh[7];
    float rb = sh[8]+sh[9]+sh[10]+sh[11]+sh[12]+sh[13]+sh[14]+sh[15];
    __syncthreads();
    return make_float2(ra, rb);
}

__device__ __forceinline__ float2 blockMax2(float a, float b) {
    __shared__ float sh[16];
    #pragma unroll
    for (int o = 16; o; o >>= 1) {
        a = fmaxf(a, __shfl_xor_sync(0xffffffffu, a, o));
        b = fmaxf(b, __shfl_xor_sync(0xffffffffu, b, o));
    }
    int w = threadIdx.x >> 5;
    if ((threadIdx.x & 31) == 0) { sh[w] = a; sh[8 + w] = b; }
    __syncthreads();
    float ra = sh[0], rb = sh[8];
    #pragma unroll
    for (int i = 1; i < 8; i++) { ra = fmaxf(ra, sh[i]); rb = fmaxf(rb, sh[8+i]); }
    __syncthreads();
    return make_float2(ra, rb);
}

__device__ __forceinline__ float geluf(float x) {
    return 0.5f * x * (1.0f + erff(x * 0.70710678118654752f));
}

// C[32, nb..nb+64) (+=bias) = X[32, k0..k0+klen) @ W[nb.., k0..]^T  (W row-major [N,ldw])
__device__ void tileA(const float* __restrict__ X, int ldx,
                      const float* __restrict__ W, int ldw,
                      int nb, int k0, int klen,
                      float* __restrict__ C, int ldc,
                      const float* __restrict__ bias) {
    float (*Xs)[33] = (float(*)[33])s_Xs;
    float (*Ws)[33] = (float(*)[33])s_Ws;
    int tid = threadIdx.x, r0 = (tid & 7) * 4, c0 = (tid >> 3) * 2;
    float acc[4][2] = {};
    for (int kc = k0; kc < k0 + klen; kc += 32) {
        __syncthreads();
        for (int i = tid; i < 1024; i += 256)
            Xs[i >> 5][i & 31] = X[(size_t)(i >> 5) * ldx + kc + (i & 31)];
        for (int i = tid; i < 2048; i += 256)
            Ws[i >> 5][i & 31] = W[(size_t)(nb + (i >> 5)) * ldw + kc + (i & 31)];
        __syncthreads();
        #pragma unroll
        for (int k = 0; k < 32; k++) {
            float xa[4], wa[2];
            #pragma unroll
            for (int i = 0; i < 4; i++) xa[i] = Xs[r0 + i][k];
            wa[0] = Ws[c0][k]; wa[1] = Ws[c0 + 1][k];
            #pragma unroll
            for (int i = 0; i < 4; i++) {
                acc[i][0] += xa[i] * wa[0];
                acc[i][1] += xa[i] * wa[1];
            }
        }
    }
    #pragma unroll
    for (int i = 0; i < 4; i++)
        #pragma unroll
        for (int j = 0; j < 2; j++) {
            float v = acc[i][j];
            if (bias) v += bias[nb + c0 + j];
            C[(size_t)(r0 + i) * ldc + nb + c0 + j] = v;
        }
}

// C[32, nb..nb+64) = X[32, k0..) @ W[k0.., nb..]  (W k-major [K,512])
__device__ void tileB(const float* __restrict__ X, int ldx,
                      const float* __restrict__ W,
                      int nb, int k0, int klen,
                      float* __restrict__ C, int ldc) {
    float (*Xs)[33] = (float(*)[33])s_Xs;
    float (*Ws2)[65] = (float(*)[65])s_Ws;
    int tid = threadIdx.x, r0 = (tid & 7) * 4, c0 = (tid >> 3) * 2;
    float acc[4][2] = {};
    for (int kc = k0; kc < k0 + klen; kc += 32) {
        __syncthreads();
        for (int i = tid; i < 1024; i += 256)
            Xs[i >> 5][i & 31] = X[(size_t)(i >> 5) * ldx + kc + (i & 31)];
        for (int i = tid; i < 2048; i += 256)
            Ws2[i >> 6][i & 63] = W[(size_t)(kc + (i >> 6)) * 512 + nb + (i & 63)];
        __syncthreads();
        #pragma unroll
        for (int k = 0; k < 32; k++) {
            float xa[4], wa[2];
            #pragma unroll
            for (int i = 0; i < 4; i++) xa[i] = Xs[r0 + i][k];
            wa[0] = Ws2[k][c0]; wa[1] = Ws2[k][c0 + 1];
            #pragma unroll
            for (int i = 0; i < 4; i++) {
                acc[i][0] += xa[i] * wa[0];
                acc[i][1] += xa[i] * wa[1];
            }
        }
    }
    #pragma unroll
    for (int i = 0; i < 4; i++)
        #pragma unroll
        for (int j = 0; j < 2; j++)
            C[(size_t)(r0 + i) * ldc + nb + c0 + j] = acc[i][j];
}

__global__ __launch_bounds__(256, 1) void mega(
        const float* __restrict__ enc,  const float* __restrict__ spec,
        const float* __restrict__ embw, const float* __restrict__ outw,
        const float* __restrict__ outb, const float* __restrict__ gum,
        const float* __restrict__ saqw, const float* __restrict__ saqb,
        const float* __restrict__ saow, const float* __restrict__ saob,
        const float* __restrict__ caqw, const float* __restrict__ caqb,
        const float* __restrict__ caow, const float* __restrict__ caob,
        const float* __restrict__ l1g,  const float* __restrict__ l1b,
        const float* __restrict__ l2g,  const float* __restrict__ l2b,
        const float* __restrict__ l3g,  const float* __restrict__ l3b,
        const float* __restrict__ w1,   const float* __restrict__ b1,
        const float* __restrict__ w2,   const float* __restrict__ b2,
        float* __restrict__ out) {
    int tid = threadIdx.x, blk = blockIdx.x, nb = gridDim.x;
    int w = tid >> 5, lane = tid & 31;

    // ---- setup: x init + EOS rows + cross-attn precompute ----
    if (blk < 32) {
        for (int e = tid; e < 512; e += 256) g_x[blk * 512 + e] = spec[e];
        float* seq = out + (size_t)blk * (17 * Vc) + (size_t)16 * Vc;
        for (int v = tid; v < Vc; v += 256) seq[v] = (v == 0) ? 1.f : 0.f;
    }
    if (blk < 128) {   // capre job: l = blk>>5, b = blk&31
        int l = blk >> 5, b = blk & 31;
        for (int e = tid; e < 512; e += 256) s_q[e] = enc[b * 512 + e];
        __syncthreads();
        for (int e = w; e < 512; e += 8) {
            const float* wr = caqw + ((size_t)l * 1536 + 1024 + e) * 512;
            float a0=0,a1=0,a2=0,a3=0;
            for (int k = lane; k < 512; k += 128) {
                a0 += wr[k]*s_q[k];       a1 += wr[k+32]*s_q[k+32];
                a2 += wr[k+64]*s_q[k+64]; a3 += wr[k+96]*s_q[k+96];
            }
            float acc = a0+a1+a2+a3;
            #pragma unroll
            for (int o = 16; o; o >>= 1) acc += __shfl_xor_sync(0xffffffffu, acc, o);
            if (lane == 0) s_o[e] = acc + caqb[l * 1536 + 1024 + e];
        }
        __syncthreads();
        for (int e = w; e < 512; e += 8) {
            const float* wr = caow + ((size_t)l * 512 + e) * 512;
            float a0=0,a1=0,a2=0,a3=0;
            for (int k = lane; k < 512; k += 128) {
                a0 += wr[k]*s_o[k];       a1 += wr[k+32]*s_o[k+32];
                a2 += wr[k+64]*s_o[k+64]; a3 += wr[k+96]*s_o[k+96];
            }
            float acc = a0+a1+a2+a3;
            #pragma unroll
            for (int o = 16; o; o >>= 1) acc += __shfl_xor_sync(0xffffffffu, acc, o);
            if (lane == 0) g_ca[((size_t)l * 32 + b) * 512 + e] = acc + caob[l * 512 + e];
        }
    }
    gsync();

    for (int s = 0; s < Tc; s++) {
        for (int l = 0; l < 4; l++) {
            // P1: qkv partials (96 jobs: 24 n-tiles x 4 k-splits)
            for (int j = blk; j < 24 * KSQ; j += nb) {
                int nt = j % 24, ks = j / 24;
                tileA(g_x, 512, saqw + (size_t)l * 1536 * 512, 512,
                      nt * 64, ks * 128, 128,
                      g_qkvp + (size_t)ks * Bc * 1536, 1536, 0);
            }
            gsync();
            // P2: attention core
            if (blk < 32) {
                int b = blk;
                const float* bp = saqb + l * 1536;
                for (int e = tid; e < 512; e += 256) {
                    float qq = bp[e], kk = bp[512 + e], vv = bp[1024 + e];
                    #pragma unroll
                    for (int p = 0; p < KSQ; p++) {
                        const float* qp = g_qkvp + ((size_t)p * 32 + b) * 1536;
                        qq += qp[e]; kk += qp[512 + e]; vv += qp[1024 + e];
                    }
                    s_q[e] = qq;
                    g_Kc [((size_t)(l * Tc + s) * Bc + b) * 512 + e] = kk;
                    g_Vcc[((size_t)(l * Tc + s) * Bc + b) * 512 + e] = vv;
                }
                __syncthreads();
                float sc = -1e30f;
                if (lane <= s) {
                    const float* kp = g_Kc + ((size_t)(l * Tc + lane) * Bc + b) * 512 + w * 64;
                    const float* qp = s_q + w * 64;
                    float a0 = 0.f, a1 = 0.f;
                    #pragma unroll
                    for (int d = 0; d < 64; d += 2) { a0 += qp[d]*kp[d]; a1 += qp[d+1]*kp[d+1]; }
                    sc = (a0 + a1) * 0.125f;
                }
                float m = sc;
                #pragma unroll
                for (int o = 16; o; o >>= 1) m = fmaxf(m, __shfl_xor_sync(0xffffffffu, m, o));
                float ex = (lane <= s) ? expf(sc - m) : 0.f;
                float sum = ex;
                #pragma unroll
                for (int o = 16; o; o >>= 1) sum += __shfl_xor_sync(0xffffffffu, sum, o);
                float a = ex / sum;
                float o0 = 0.f, o1 = 0.f;
                for (int j = 0; j <= s; j++) {
                    float aj = __shfl_sync(0xffffffffu, a, j);
                    const float* vp = g_Vcc + ((size_t)(l * Tc + j) * Bc + b) * 512 + w * 64;
                    o0 += aj * vp[lane]; o1 += aj * vp[lane + 32];
                }
                g_attn_o[b * 512 + w * 64 + lane] = o0;
                g_attn_o[b * 512 + w * 64 + lane + 32] = o1;
            }
            gsync();
            // P3: out-proj partials (64 jobs: 8 n-tiles x 8 k-splits)
            for (int j = blk; j < 8 * KSO; j += nb) {
                int nt = j % 8, ks = j / 8;
                tileA(g_attn_o, 512, saow + (size_t)l * 512 * 512, 512,
                      nt * 64, ks * 64, 64,
                      g_opp + (size_t)ks * Bc * 512, 512, 0);
            }
            gsync();
            // P4: residual + LN1 + CA + LN2
            if (blk < 32) {
                int b = blk;
                for (int e = tid; e < 512; e += 256) {
                    float v = g_x[b * 512 + e] + saob[l * 512 + e];
                    #pragma unroll
                    for (int p = 0; p < KSO; p++) v += g_opp[((size_t)p * 32 + b) * 512 + e];
                    s_q[e] = v;
                }
                __syncthreads();
                float s1 = 0.f, s2 = 0.f;
                for (int e = tid; e < 512; e += 256) { float v = s_q[e]; s1 += v; s2 += v*v; }
                float2 r = blockSum2(s1, s2);
                float mean = r.x * (1.f/512.f);
                float rstd = rsqrtf(r.y * (1.f/512.f) - mean*mean + 1e-5f);
                for (int e = tid; e < 512; e += 256)
                    s_o[e] = (s_q[e]-mean)*rstd*l1g[l*512+e] + l1b[l*512+e]
                           + g_ca[((size_t)l*32+b)*512+e];
                __syncthreads();
                float t1 = 0.f, t2 = 0.f;
                for (int e = tid; e < 512; e += 256) { float v = s_o[e]; t1 += v; t2 += v*v; }
                r = blockSum2(t1, t2);
                mean = r.x * (1.f/512.f);
                rstd = rsqrtf(r.y * (1.f/512.f) - mean*mean + 1e-5f);
                for (int e = tid; e < 512; e += 256)
                    g_x[b*512+e] = (s_o[e]-mean)*rstd*l2g[l*512+e] + l2b[l*512+e];
            }
            gsync();
            // P5: ff1 partials (128 jobs: 32 n-tiles x 4 k-splits)
            for (int j = blk; j < 32 * KSF1; j += nb) {
                int nt = j % 32, ks = j / 32;
                tileA(g_x, 512, w1 + (size_t)l * 2048 * 512, 512,
                      nt * 64, ks * 128, 128,
                      g_ff1p + (size_t)ks * Bc * 2048, 2048, 0);
            }
            gsync();
            // P6: gelu(sum + b1) -> g_h
            for (int i = blk * 256 + tid; i < 32 * 2048; i += nb * 256) {
                int b = i >> 11, k = i & 2047;
                float u = b1[l * 2048 + k];
                #pragma unroll
                for (int p = 0; p < KSF1; p++) u += g_ff1p[((size_t)p * 32 + b) * 2048 + k];
                g_h[i] = geluf(u);
            }
            gsync();
            // P7: ff2 partials (128 jobs: 8 n-tiles x 16 k-splits)
            for (int j = blk; j < 8 * KSF2; j += nb) {
                int nt = j % 8, ks = j / 8;
                tileA(g_h, 2048, w2 + (size_t)l * 512 * 2048, 2048,
                      nt * 64, ks * 128, 128,
                      g_ff2p + (size_t)ks * Bc * 512, 512, 0);
            }
            gsync();
            // P8: residual + LN3
            if (blk < 32) {
                int b = blk;
                for (int e = tid; e < 512; e += 256) {
                    float v = g_x[b * 512 + e] + b2[l * 512 + e];
                    #pragma unroll
                    for (int p = 0; p < KSF2; p++) v += g_ff2p[((size_t)p * 32 + b) * 512 + e];
                    s_q[e] = v;
                }
                __syncthreads();
                float s1 = 0.f, s2 = 0.f;
                for (int e = tid; e < 512; e += 256) { float v = s_q[e]; s1 += v; s2 += v*v; }
                float2 r = blockSum2(s1, s2);
                float mean = r.x * (1.f/512.f);
                float rstd = rsqrtf(r.y * (1.f/512.f) - mean*mean + 1e-5f);
                for (int e = tid; e < 512; e += 256)
                    g_x[b*512+e] = (s_q[e]-mean)*rstd*l3g[l*512+e] + l3b[l*512+e];
            }
            gsync();
        }
        // P9: logits = x @ outw^T + outb  (128 jobs, no k-split)
        for (int j = blk; j < 128; j += nb)
            tileA(g_x, 512, outw, 512, j * 64, 0, 512, g_logits, Vc, outb);
        gsync();
        // P10: softmaxes + outputs + sample
        if (blk < 32) {
            int b = blk;
            const float* gp = gum + ((size_t)s * Bc + b) * Vc;
            float* lg = g_logits + (size_t)b * Vc;
            float mx1 = -1e30f, mx2 = -1e30f;
            for (int v = tid; v < Vc; v += 256) {
                float x = lg[v];
                mx1 = fmaxf(mx1, x);
                mx2 = fmaxf(mx2, x + gp[v]);
            }
            float2 M = blockMax2(mx1, mx2);
            float z1 = 0.f, z2 = 0.f;
            for (int v = tid; v < Vc; v += 256) {
                float x = lg[v];
                z1 += expf(x - M.x);
                z2 += expf(x + gp[v] - M.y);
            }
            float2 Z = blockSum2(z1, z2);
            float i1 = 1.f / Z.x, i2 = 1.f / Z.y;
            float* seq = out + (size_t)b * (17 * Vc) + (size_t)s * Vc;
            float* dst = out + (size_t)Bc * 17 * Vc + ((size_t)s * Bc + b) * Vc;
            float* smp = g_sample + (size_t)b * Vc;
            for (int v = tid; v < Vc; v += 256) {
                float x = lg[v];
                dst[v] = expf(x - M.x) * i1;
                float sv = expf(x + gp[v] - M.y) * i2;
                seq[v] = sv;
                smp[v] = sv;
            }
        }
        gsync();
        if (s < Tc - 1) {
            // P11: embed partials (128 jobs: 8 n-tiles x 16 k-splits)
            for (int j = blk; j < 8 * KSE; j += nb) {
                int nt = j % 8, ks = j / 8;
                tileB(g_sample, Vc, embw, nt * 64, ks * 512, 512,
                      g_embp + (size_t)ks * Bc * 512, 512);
            }
            gsync();
            // P12: x = sum(embed partials) * sqrt(E)
            if (blk < 32) {
                int b = blk;
                for (int e = tid; e < 512; e += 256) {
                    float a = 0.f;
                    #pragma unroll
                    for (int p = 0; p < KSE; p++) a += g_embp[((size_t)p * 32 + b) * 512 + e];
                    g_x[b * 512 + e] = a * EMB_SCALE;
                }
            }
            gsync();
        }
    }
}

extern "C" void kernel_launch(void* const* d_in, const int* in_sizes, int n_in,
                              void* d_out, int out_size) {
    const float* enc  = (const float*)d_in[0];
    const float* spec = (const float*)d_in[1];
    const float* embw = (const float*)d_in[2];
    const float* outw = (const float*)d_in[3];
    const float* outb = (const float*)d_in[4];
    const float* gum  = (const float*)d_in[5];
    const float* saqw = (const float*)d_in[6];
    const float* saqb = (const float*)d_in[7];
    const float* saow = (const float*)d_in[8];
    const float* saob = (const float*)d_in[9];
    const float* caqw = (const float*)d_in[10];
    const float* caqb = (const float*)d_in[11];
    const float* caow = (const float*)d_in[12];
    const float* caob = (const float*)d_in[13];
    const float* l1g  = (const float*)d_in[14];
    const float* l1b  = (const float*)d_in[15];
    const float* l2g  = (const float*)d_in[16];
    const float* l2b  = (const float*)d_in[17];
    const float* l3g  = (const float*)d_in[18];
    const float* l3b  = (const float*)d_in[19];
    const float* w1   = (const float*)d_in[20];
    const float* b1   = (const float*)d_in[21];
    const float* w2   = (const float*)d_in[22];
    const float* b2   = (const float*)d_in[23];

    int dev = 0;
    cudaGetDevice(&dev);
    int sms = 0;
    cudaDeviceGetAttribute(&sms, cudaDevAttrMultiProcessorCount, dev);
    if (sms < 1) sms = 148;

    mega<<<sms, 256>>>(enc, spec, embw, outw, outb, gum,
                       saqw, saqb, saow, saob, caqw, caqb, caow, caob,
                       l1g, l1b, l2g, l2b, l3g, l3b, w1, b1, w2, b2,
                       (float*)d_out);
}

// round 6
// speedup vs baseline: 3.0658x; 1.3651x over previous
#include <cuda_runtime.h>
#include <math.h>
#include <stdint.h>

#define Bc 32
#define Vc 8192
#define Tc 16
#define EMB_SCALE 22.627416997969522f
#define KSQ 16
#define KSO 16
#define KSF1 16
#define KSF2 64
#define KSL 4
#define KSE 64

__device__ float g_x[Bc * 512];
__device__ float g_attn_o[Bc * 512];
__device__ float g_qkvp[KSQ * Bc * 1536];
__device__ float g_opp[KSO * Bc * 512];
__device__ float g_ff1p[KSF1 * Bc * 2048];
__device__ float g_ff2p[KSF2 * Bc * 512];
__device__ float g_logp[KSL * Bc * Vc];
__device__ float g_embp[KSE * Bc * 512];
__device__ float g_logits[Bc * Vc];
__device__ float g_sample[Bc * Vc];
__device__ float g_ca[4 * Bc * 512];
__device__ float g_Kc[4 * Tc * Bc * 512];
__device__ float g_Vcc[4 * Tc * Bc * 512];

__device__ int g_count;
__device__ volatile int g_gen;

__shared__ float s_Xs[32 * 33];       // X tile [row][k], pad 33
__shared__ float s_Ws[256 * 33];      // W tile [col][k] pad 33, or [k][col] pad 260 (8320<8448)
__shared__ float s_q[512];
__shared__ float s_o[512];

__device__ __forceinline__ void gsync() {
    __threadfence();
    __syncthreads();
    if (threadIdx.x == 0) {
        int gen = g_gen;
        if (atomicAdd(&g_count, 1) == (int)gridDim.x - 1) {
            g_count = 0;
            __threadfence();
            g_gen = gen + 1;
        } else {
            while (g_gen == gen) { }
        }
        __threadfence();
    }
    __syncthreads();
}

__device__ __forceinline__ float2 blockSum2(float a, float b) {
    __shared__ float sh[16];
    #pragma unroll
    for (int o = 16; o; o >>= 1) {
        a += __shfl_xor_sync(0xffffffffu, a, o);
        b += __shfl_xor_sync(0xffffffffu, b, o);
    }
    int w = threadIdx.x >> 5;
    if ((threadIdx.x & 31) == 0) { sh[w] = a; sh[8 + w] = b; }
    __syncthreads();
    float ra = sh[0]+sh[1]+sh[2]+sh[3]+sh[4]+sh[5]+sh[6]+sh[7];
    float rb = sh[8]+sh[9]+sh[10]+sh[11]+sh[12]+sh[13]+sh[14]+sh[15];
    __syncthreads();
    return make_float2(ra, rb);
}

__device__ __forceinline__ float2 blockMax2(float a, float b) {
    __shared__ float sh[16];
    #pragma unroll
    for (int o = 16; o; o >>= 1) {
        a = fmaxf(a, __shfl_xor_sync(0xffffffffu, a, o));
        b = fmaxf(b, __shfl_xor_sync(0xffffffffu, b, o));
    }
    int w = threadIdx.x >> 5;
    if ((threadIdx.x & 31) == 0) { sh[w] = a; sh[8 + w] = b; }
    __syncthreads();
    float ra = sh[0], rb = sh[8];
    #pragma unroll
    for (int i = 1; i < 8; i++) { ra = fmaxf(ra, sh[i]); rb = fmaxf(rb, sh[8+i]); }
    __syncthreads();
    return make_float2(ra, rb);
}

__device__ __forceinline__ float geluf(float x) {
    return 0.5f * x * (1.0f + erff(x * 0.70710678118654752f));
}

// ---- staging (all conflict-free; float4 global reads) ----
__device__ __forceinline__ void stage_X(const float* __restrict__ X, int ldx, int kc) {
    float (*Xs)[33] = (float(*)[33])s_Xs;
    int i = threadIdx.x;              // 256 f4 loads exactly
    int r = i >> 3, kq = i & 7;
    float4 v = *(const float4*)(X + (size_t)r * ldx + kc + kq * 4);
    Xs[r][kq*4+0] = v.x; Xs[r][kq*4+1] = v.y; Xs[r][kq*4+2] = v.z; Xs[r][kq*4+3] = v.w;
}

// W row-major [N, ldw]; stage rows nb..nb+256, k-chunk kc..kc+32 -> Ws[c][k]
__device__ __forceinline__ void stage_W_A(const float* __restrict__ W, int ldw, int nb, int kc) {
    float (*Ws)[33] = (float(*)[33])s_Ws;
    #pragma unroll
    for (int i = threadIdx.x; i < 2048; i += 256) {
        int c = i >> 3, kq = i & 7;
        float4 v = *(const float4*)(W + (size_t)(nb + c) * ldw + kc + kq * 4);
        Ws[c][kq*4+0] = v.x; Ws[c][kq*4+1] = v.y; Ws[c][kq*4+2] = v.z; Ws[c][kq*4+3] = v.w;
    }
}

// W k-major [K, ldw]; stage cols nb..nb+256, rows kc..kc+32 -> Wk[k][c]
__device__ __forceinline__ void stage_W_B(const float* __restrict__ W, int ldw, int nb, int kc) {
    float (*Wk)[260] = (float(*)[260])s_Ws;
    #pragma unroll
    for (int i = threadIdx.x; i < 2048; i += 256) {
        int k = i >> 6, cq = i & 63;
        float4 v = *(const float4*)(W + (size_t)(kc + k) * ldw + nb + cq * 4);
        *(float4*)&Wk[k][cq * 4] = v;
    }
}

__device__ __forceinline__ void inner_A(float acc[4][8], int r0, int c0) {
    float (*Xs)[33] = (float(*)[33])s_Xs;
    float (*Ws)[33] = (float(*)[33])s_Ws;
    #pragma unroll 4
    for (int k = 0; k < 32; k++) {
        float xa[4], wa[8];
        #pragma unroll
        for (int i = 0; i < 4; i++) xa[i] = Xs[r0 + i][k];
        #pragma unroll
        for (int j = 0; j < 8; j++) wa[j] = Ws[c0 + j][k];
        #pragma unroll
        for (int i = 0; i < 4; i++)
            #pragma unroll
            for (int j = 0; j < 8; j++) acc[i][j] += xa[i] * wa[j];
    }
}

__device__ __forceinline__ void inner_B(float acc[4][8], int r0, int c0) {
    float (*Xs)[33] = (float(*)[33])s_Xs;
    float (*Wk)[260] = (float(*)[260])s_Ws;
    #pragma unroll 4
    for (int k = 0; k < 32; k++) {
        float xa[4], wa[8];
        #pragma unroll
        for (int i = 0; i < 4; i++) xa[i] = Xs[r0 + i][k];
        #pragma unroll
        for (int j = 0; j < 8; j++) wa[j] = Wk[k][c0 + j];
        #pragma unroll
        for (int i = 0; i < 4; i++)
            #pragma unroll
            for (int j = 0; j < 8; j++) acc[i][j] += xa[i] * wa[j];
    }
}

__device__ __forceinline__ void store_acc(float acc[4][8], int r0, int c0,
                                          float* __restrict__ C, int ldc, int nb) {
    #pragma unroll
    for (int i = 0; i < 4; i++) {
        float4* p = (float4*)(C + (size_t)(r0 + i) * ldc + nb + c0);
        p[0] = make_float4(acc[i][0], acc[i][1], acc[i][2], acc[i][3]);
        p[1] = make_float4(acc[i][4], acc[i][5], acc[i][6], acc[i][7]);
    }
}

__global__ __launch_bounds__(256, 1) void mega(
        const float* __restrict__ enc,  const float* __restrict__ spec,
        const float* __restrict__ embw, const float* __restrict__ outw,
        const float* __restrict__ outb, const float* __restrict__ gum,
        const float* __restrict__ saqw, const float* __restrict__ saqb,
        const float* __restrict__ saow, const float* __restrict__ saob,
        const float* __restrict__ caqw, const float* __restrict__ caqb,
        const float* __restrict__ caow, const float* __restrict__ caob,
        const float* __restrict__ l1g,  const float* __restrict__ l1b,
        const float* __restrict__ l2g,  const float* __restrict__ l2b,
        const float* __restrict__ l3g,  const float* __restrict__ l3b,
        const float* __restrict__ w1,   const float* __restrict__ b1,
        const float* __restrict__ w2,   const float* __restrict__ b2,
        float* __restrict__ out) {
    int tid = threadIdx.x, blk = blockIdx.x, nbk = gridDim.x;
    int w = tid >> 5, lane = tid & 31;
    int r0 = (tid & 7) * 4, c0 = (tid >> 3) * 8;

    // ---- setup: x init + EOS rows + cross-attn precompute ----
    if (blk < 32) {
        for (int e = tid; e < 512; e += 256) g_x[blk * 512 + e] = spec[e];
        float* seq = out + (size_t)blk * (17 * Vc) + (size_t)16 * Vc;
        for (int v = tid; v < Vc; v += 256) seq[v] = (v == 0) ? 1.f : 0.f;
    }
    if (blk < 128) {
        int l = blk >> 5, b = blk & 31;
        for (int e = tid; e < 512; e += 256) s_q[e] = enc[b * 512 + e];
        __syncthreads();
        for (int e = w; e < 512; e += 8) {
            const float* wr = caqw + ((size_t)l * 1536 + 1024 + e) * 512;
            float a0=0,a1=0,a2=0,a3=0;
            for (int k = lane; k < 512; k += 128) {
                a0 += wr[k]*s_q[k];       a1 += wr[k+32]*s_q[k+32];
                a2 += wr[k+64]*s_q[k+64]; a3 += wr[k+96]*s_q[k+96];
            }
            float acc = a0+a1+a2+a3;
            #pragma unroll
            for (int o = 16; o; o >>= 1) acc += __shfl_xor_sync(0xffffffffu, acc, o);
            if (lane == 0) s_o[e] = acc + caqb[l * 1536 + 1024 + e];
        }
        __syncthreads();
        for (int e = w; e < 512; e += 8) {
            const float* wr = caow + ((size_t)l * 512 + e) * 512;
            float a0=0,a1=0,a2=0,a3=0;
            for (int k = lane; k < 512; k += 128) {
                a0 += wr[k]*s_o[k];       a1 += wr[k+32]*s_o[k+32];
                a2 += wr[k+64]*s_o[k+64]; a3 += wr[k+96]*s_o[k+96];
            }
            float acc = a0+a1+a2+a3;
            #pragma unroll
            for (int o = 16; o; o >>= 1) acc += __shfl_xor_sync(0xffffffffu, acc, o);
            if (lane == 0) g_ca[((size_t)l * 32 + b) * 512 + e] = acc + caob[l * 512 + e];
        }
    }
    gsync();

    for (int s = 0; s < Tc; s++) {
        for (int l = 0; l < 4; l++) {
            // P1: qkv partials: 96 jobs = 6 nt x 16 ks, klen 32
            for (int j = blk; j < 6 * KSQ; j += nbk) {
                int ks = j & 15, nt = j >> 4;
                float acc[4][8] = {};
                __syncthreads();
                stage_X(g_x, 512, ks * 32);
                stage_W_A(saqw + (size_t)l * 1536 * 512, 512, nt * 256, ks * 32);
                __syncthreads();
                inner_A(acc, r0, c0);
                store_acc(acc, r0, c0, g_qkvp + (size_t)ks * 32 * 1536, 1536, nt * 256);
            }
            gsync();
            // P2: attention core (32 blocks)
            if (blk < 32) {
                int b = blk;
                const float* bp = saqb + l * 1536;
                for (int e = tid; e < 512; e += 256) {
                    float qq = bp[e], kk = bp[512 + e], vv = bp[1024 + e];
                    #pragma unroll
                    for (int p = 0; p < KSQ; p++) {
                        const float* qp = g_qkvp + ((size_t)p * 32 + b) * 1536;
                        qq += qp[e]; kk += qp[512 + e]; vv += qp[1024 + e];
                    }
                    s_q[e] = qq;
                    g_Kc [((size_t)(l * Tc + s) * Bc + b) * 512 + e] = kk;
                    g_Vcc[((size_t)(l * Tc + s) * Bc + b) * 512 + e] = vv;
                }
                __syncthreads();
                float sc = -1e30f;
                if (lane <= s) {
                    const float* kp = g_Kc + ((size_t)(l * Tc + lane) * Bc + b) * 512 + w * 64;
                    const float* qp = s_q + w * 64;
                    float a0 = 0.f, a1 = 0.f;
                    #pragma unroll
                    for (int d = 0; d < 64; d += 2) { a0 += qp[d]*kp[d]; a1 += qp[d+1]*kp[d+1]; }
                    sc = (a0 + a1) * 0.125f;
                }
                float m = sc;
                #pragma unroll
                for (int o = 16; o; o >>= 1) m = fmaxf(m, __shfl_xor_sync(0xffffffffu, m, o));
                float ex = (lane <= s) ? expf(sc - m) : 0.f;
                float sum = ex;
                #pragma unroll
                for (int o = 16; o; o >>= 1) sum += __shfl_xor_sync(0xffffffffu, sum, o);
                float a = ex / sum;
                float o0 = 0.f, o1 = 0.f;
                for (int j = 0; j <= s; j++) {
                    float aj = __shfl_sync(0xffffffffu, a, j);
                    const float* vp = g_Vcc + ((size_t)(l * Tc + j) * Bc + b) * 512 + w * 64;
                    o0 += aj * vp[lane]; o1 += aj * vp[lane + 32];
                }
                g_attn_o[b * 512 + w * 64 + lane] = o0;
                g_attn_o[b * 512 + w * 64 + lane + 32] = o1;
            }
            gsync();
            // P3: out-proj partials: 32 jobs = 2 nt x 16 ks, klen 32
            for (int j = blk; j < 2 * KSO; j += nbk) {
                int nt = j & 1, ks = j >> 1;
                float acc[4][8] = {};
                __syncthreads();
                stage_X(g_attn_o, 512, ks * 32);
                stage_W_A(saow + (size_t)l * 512 * 512, 512, nt * 256, ks * 32);
                __syncthreads();
                inner_A(acc, r0, c0);
                store_acc(acc, r0, c0, g_opp + (size_t)ks * 32 * 512, 512, nt * 256);
            }
            gsync();
            // P4: residual + LN1 + CA + LN2 (32 blocks)
            if (blk < 32) {
                int b = blk;
                for (int e = tid; e < 512; e += 256) {
                    float v = g_x[b * 512 + e] + saob[l * 512 + e];
                    #pragma unroll
                    for (int p = 0; p < KSO; p++) v += g_opp[((size_t)p * 32 + b) * 512 + e];
                    s_q[e] = v;
                }
                __syncthreads();
                float s1 = 0.f, s2 = 0.f;
                for (int e = tid; e < 512; e += 256) { float v = s_q[e]; s1 += v; s2 += v*v; }
                float2 r = blockSum2(s1, s2);
                float mean = r.x * (1.f/512.f);
                float rstd = rsqrtf(r.y * (1.f/512.f) - mean*mean + 1e-5f);
                for (int e = tid; e < 512; e += 256)
                    s_o[e] = (s_q[e]-mean)*rstd*l1g[l*512+e] + l1b[l*512+e]
                           + g_ca[((size_t)l*32+b)*512+e];
                __syncthreads();
                float t1 = 0.f, t2 = 0.f;
                for (int e = tid; e < 512; e += 256) { float v = s_o[e]; t1 += v; t2 += v*v; }
                r = blockSum2(t1, t2);
                mean = r.x * (1.f/512.f);
                rstd = rsqrtf(r.y * (1.f/512.f) - mean*mean + 1e-5f);
                for (int e = tid; e < 512; e += 256)
                    g_x[b*512+e] = (s_o[e]-mean)*rstd*l2g[l*512+e] + l2b[l*512+e];
            }
            gsync();
            // P5: ff1 partials: 128 jobs = 8 nt x 16 ks, klen 32
            for (int j = blk; j < 8 * KSF1; j += nbk) {
                int ks = j & 15, nt = j >> 4;
                float acc[4][8] = {};
                __syncthreads();
                stage_X(g_x, 512, ks * 32);
                stage_W_A(w1 + (size_t)l * 2048 * 512, 512, nt * 256, ks * 32);
                __syncthreads();
                inner_A(acc, r0, c0);
                store_acc(acc, r0, c0, g_ff1p + (size_t)ks * 32 * 2048, 2048, nt * 256);
            }
            gsync();
            // P7: ff2 partials with folded gelu: 128 jobs = 2 nt x 64 ks, klen 32
            for (int j = blk; j < 2 * KSF2; j += nbk) {
                int nt = j & 1, ks = j >> 1;
                int kc = ks * 32;
                float acc[4][8] = {};
                __syncthreads();
                {   // Xs[r][k] = gelu(b1 + sum of ff1 partials)
                    float (*Xs)[33] = (float(*)[33])s_Xs;
                    for (int i = tid; i < 1024; i += 256) {
                        int r = i >> 5, k = i & 31;
                        float u = b1[l * 2048 + kc + k];
                        #pragma unroll
                        for (int p = 0; p < KSF1; p++)
                            u += g_ff1p[((size_t)(p * 32) + r) * 2048 + kc + k];
                        Xs[r][k] = geluf(u);
                    }
                }
                stage_W_A(w2 + (size_t)l * 512 * 2048, 2048, nt * 256, kc);
                __syncthreads();
                inner_A(acc, r0, c0);
                store_acc(acc, r0, c0, g_ff2p + (size_t)ks * 32 * 512, 512, nt * 256);
            }
            gsync();
            // P8: residual + LN3 (32 blocks)
            if (blk < 32) {
                int b = blk;
                for (int e = tid; e < 512; e += 256) {
                    float v = g_x[b * 512 + e] + b2[l * 512 + e];
                    #pragma unroll
                    for (int p = 0; p < KSF2; p++) v += g_ff2p[((size_t)p * 32 + b) * 512 + e];
                    s_q[e] = v;
                }
                __syncthreads();
                float s1 = 0.f, s2 = 0.f;
                for (int e = tid; e < 512; e += 256) { float v = s_q[e]; s1 += v; s2 += v*v; }
                float2 r = blockSum2(s1, s2);
                float mean = r.x * (1.f/512.f);
                float rstd = rsqrtf(r.y * (1.f/512.f) - mean*mean + 1e-5f);
                for (int e = tid; e < 512; e += 256)
                    g_x[b*512+e] = (s_q[e]-mean)*rstd*l3g[l*512+e] + l3b[l*512+e];
            }
            gsync();
        }
        // P9: logits partials: 128 jobs = 32 nt x 4 ks, klen 128
        for (int j = blk; j < 32 * KSL; j += nbk) {
            int ks = j & 3, nt = j >> 2;
            float acc[4][8] = {};
            for (int kc = ks * 128; kc < ks * 128 + 128; kc += 32) {
                __syncthreads();
                stage_X(g_x, 512, kc);
                stage_W_A(outw, 512, nt * 256, kc);
                __syncthreads();
                inner_A(acc, r0, c0);
            }
            store_acc(acc, r0, c0, g_logp + (size_t)ks * 32 * Vc, Vc, nt * 256);
        }
        gsync();
        // P10: softmaxes + outputs + sample (32 blocks)
        if (blk < 32) {
            int b = blk;
            const float* gp = gum + ((size_t)s * Bc + b) * Vc;
            float* lg = g_logits + (size_t)b * Vc;
            float mx1 = -1e30f, mx2 = -1e30f;
            for (int v = tid; v < Vc; v += 256) {
                float x = outb[v];
                #pragma unroll
                for (int p = 0; p < KSL; p++) x += g_logp[((size_t)p * 32 + b) * Vc + v];
                lg[v] = x;
                mx1 = fmaxf(mx1, x);
                mx2 = fmaxf(mx2, x + gp[v]);
            }
            float2 M = blockMax2(mx1, mx2);
            float z1 = 0.f, z2 = 0.f;
            for (int v = tid; v < Vc; v += 256) {
                float x = lg[v];
                z1 += expf(x - M.x);
                z2 += expf(x + gp[v] - M.y);
            }
            float2 Z = blockSum2(z1, z2);
            float i1 = 1.f / Z.x, i2 = 1.f / Z.y;
            float* seq = out + (size_t)b * (17 * Vc) + (size_t)s * Vc;
            float* dst = out + (size_t)Bc * 17 * Vc + ((size_t)s * Bc + b) * Vc;
            float* smp = g_sample + (size_t)b * Vc;
            for (int v = tid; v < Vc; v += 256) {
                float x = lg[v];
                dst[v] = expf(x - M.x) * i1;
                float sv = expf(x + gp[v] - M.y) * i2;
                seq[v] = sv;
                smp[v] = sv;
            }
        }
        gsync();
        if (s < Tc - 1) {
            // P11: embed partials: 128 jobs = 2 nt x 64 ks, klen 128 (W k-major)
            for (int j = blk; j < 2 * KSE; j += nbk) {
                int nt = j & 1, ks = j >> 1;
                float acc[4][8] = {};
                for (int kc = ks * 128; kc < ks * 128 + 128; kc += 32) {
                    __syncthreads();
                    stage_X(g_sample, Vc, kc);
                    stage_W_B(embw, 512, nt * 256, kc);
                    __syncthreads();
                    inner_B(acc, r0, c0);
                }
                store_acc(acc, r0, c0, g_embp + (size_t)ks * 32 * 512, 512, nt * 256);
            }
            gsync();
            // P12: x = sum(embed partials) * sqrt(E) (32 blocks)
            if (blk < 32) {
                int b = blk;
                for (int e = tid; e < 512; e += 256) {
                    float a = 0.f;
                    #pragma unroll
                    for (int p = 0; p < KSE; p++) a += g_embp[((size_t)p * 32 + b) * 512 + e];
                    g_x[b * 512 + e] = a * EMB_SCALE;
                }
            }
            gsync();
        }
    }
}

extern "C" void kernel_launch(void* const* d_in, const int* in_sizes, int n_in,
                              void* d_out, int out_size) {
    const float* enc  = (const float*)d_in[0];
    const float* spec = (const float*)d_in[1];
    const float* embw = (const float*)d_in[2];
    const float* outw = (const float*)d_in[3];
    const float* outb = (const float*)d_in[4];
    const float* gum  = (const float*)d_in[5];
    const float* saqw = (const float*)d_in[6];
    const float* saqb = (const float*)d_in[7];
    const float* saow = (const float*)d_in[8];
    const float* saob = (const float*)d_in[9];
    const float* caqw = (const float*)d_in[10];
    const float* caqb = (const float*)d_in[11];
    const float* caow = (const float*)d_in[12];
    const float* caob = (const float*)d_in[13];
    const float* l1g  = (const float*)d_in[14];
    const float* l1b  = (const float*)d_in[15];
    const float* l2g  = (const float*)d_in[16];
    const float* l2b  = (const float*)d_in[17];
    const float* l3g  = (const float*)d_in[18];
    const float* l3b  = (const float*)d_in[19];
    const float* w1   = (const float*)d_in[20];
    const float* b1   = (const float*)d_in[21];
    const float* w2   = (const float*)d_in[22];
    const float* b2   = (const float*)d_in[23];

    int dev = 0;
    cudaGetDevice(&dev);
    int sms = 0;
    cudaDeviceGetAttribute(&sms, cudaDevAttrMultiProcessorCount, dev);
    if (sms < 1) sms = 148;

    mega<<<sms, 256>>>(enc, spec, embw, outw, outb, gum,
                       saqw, saqb, saow, saob, caqw, caqb, caow, caob,
                       l1g, l1b, l2g, l2b, l3g, l3b, w1, b1, w2, b2,
                       (float*)d_out);
}